// round 6
// baseline (speedup 1.0000x reference)
#include <cuda_runtime.h>

// CARAFE: features [2,64,64,256] f32, masks [2,128,128,25] f32, k=5, group=1.
// Nearest 64->128 half-pixel => src = dst >> 1; each source pixel feeds a 2x2
// output block sharing its 5x5 patch.
// R6: stage the full 5x12x256 feature halo tile in shared memory once per
//     block; main loop is pure LDS+FFMA (no register window, no mid-loop LDG).
//     float4 channel groups (LDS:FFMA = 1:8 incl. masks), 256 threads/block.

#define FH 64
#define FW 64
#define C4 64      // 256 channels / 4 (float4 groups)
#define OH 128
#define OW 128
#define KK 25
#define SEGW 8
#define TROWS 5
#define TCOLS 12   // SEGW + 4 halo

#define TILE_F4     (TROWS * TCOLS * C4)   // 3840 float4 = 61440 B
#define SMASK_FLTS  (SEGW * KK * 4)        // 800 floats  =  3200 B
#define SMEM_BYTES  (TILE_F4 * 16 + SMASK_FLTS * 4)   // 64640 B

__device__ __forceinline__ void fma4(float4& a, const float4 f, const float m) {
    a.x = fmaf(f.x, m, a.x);
    a.y = fmaf(f.y, m, a.y);
    a.z = fmaf(f.z, m, a.z);
    a.w = fmaf(f.w, m, a.w);
}

__global__ __launch_bounds__(256)
void carafe_kernel(const float4* __restrict__ F,
                   const float* __restrict__ masks,
                   float4* __restrict__ O)
{
    extern __shared__ __align__(16) unsigned char smraw[];
    float4* tile  = (float4*)smraw;                    // [row5][col12][c4 64]
    float*  smask = (float*)(smraw + TILE_F4 * 16);    // [px8][tap25][out4]

    const int tid = threadIdx.x;
    const int seg = blockIdx.x;
    const int hs  = blockIdx.y;
    const int b   = blockIdx.z;
    const int ws0 = seg * SEGW;

    // ---- stage feature halo tile: 3840 float4, zero-padded at borders ----
    #pragma unroll
    for (int i = 0; i < TILE_F4 / 256; i++) {          // 15 iters
        int idx = tid + i * 256;
        int c4  = idx & 63;
        int cr  = idx >> 6;            // 0..59
        int col = cr % TCOLS;
        int row = cr / TCOLS;
        int hr  = hs - 2 + row;
        int wc  = ws0 - 2 + col;
        float4 v = make_float4(0.f, 0.f, 0.f, 0.f);
        if (hr >= 0 && hr < FH && wc >= 0 && wc < FW)
            v = F[((b * FH + hr) * FW + wc) * C4 + c4];
        tile[idx] = v;
    }

    // ---- stage masks: 2 output rows x 16 output cols x 25 taps = 800 floats ----
    {
        const int mrow0 = ((b * OH + 2 * hs) * OW + 2 * ws0) * KK;
        #pragma unroll
        for (int it = 0; it < 4; it++) {
            int idx = tid + it * 256;
            if (idx < 800) {
                int oy   = idx / 400;
                int j    = idx - oy * 400;     // contiguous in global mask row
                int wrel = j / KK;             // 0..15 output col in segment
                int p    = j - wrel * KK;      // tap
                int px   = wrel >> 1;          // source col in segment
                int ox   = wrel & 1;
                float v = masks[mrow0 + oy * OW * KK + j];
                smask[px * (KK * 4) + p * 4 + oy * 2 + ox] = v;
            }
        }
    }
    __syncthreads();

    const int c4  = tid & 63;          // float4 channel group
    const int px0 = (tid >> 6) * 2;    // this thread's source-pixel pair

    #pragma unroll
    for (int sp = 0; sp < 2; sp++) {
        const int s = px0 + sp;
        const float4* tp = tile + s * C4 + c4;                  // tile[0][s][c4]
        const float4* mp = (const float4*)(smask + s * (KK * 4));

        float4 a0 = make_float4(0.f, 0.f, 0.f, 0.f);
        float4 a1 = a0, a2 = a0, a3 = a0;

        #pragma unroll
        for (int p = 0; p < KK; p++) {
            const int r = p / 5;
            const int d = p % 5;
            const float4 f = tp[(r * TCOLS + d) * C4];   // immediate smem offset
            const float4 m = mp[p];                      // broadcast LDS.128
            fma4(a0, f, m.x);   // (oy0, ox0)
            fma4(a1, f, m.y);   // (oy0, ox1)
            fma4(a2, f, m.z);   // (oy1, ox0)
            fma4(a3, f, m.w);   // (oy1, ox1)
        }

        const int ob = ((b * OH + 2 * hs) * OW + 2 * (ws0 + s)) * C4 + c4;
        O[ob]               = a0;
        O[ob + C4]          = a1;
        O[ob + OW * C4]     = a2;
        O[ob + OW * C4 + C4] = a3;
    }
}

extern "C" void kernel_launch(void* const* d_in, const int* in_sizes, int n_in,
                              void* d_out, int out_size) {
    const float4* features = (const float4*)d_in[0];
    const float*  masks    = (const float*)d_in[1];
    float4* out            = (float4*)d_out;

    cudaFuncSetAttribute(carafe_kernel,
                         cudaFuncAttributeMaxDynamicSharedMemorySize,
                         SMEM_BYTES);

    dim3 grid(FW / SEGW, FH, 2);   // (8, 64, 2) = 1024 blocks x 8 warps
    carafe_kernel<<<grid, 256, SMEM_BYTES>>>(features, masks, out);
}

// round 7
// speedup vs baseline: 1.0700x; 1.0700x over previous
#include <cuda_runtime.h>

// CARAFE: features [2,64,64,256] f32, masks [2,128,128,25] f32, k=5, group=1.
// Nearest 64->128 half-pixel => src = dst >> 1; each source pixel feeds a 2x2
// output block sharing its 5x5 patch.
// R7: R4 skeleton + latency fixes: d-major tap order (fresh column used in the
//     LAST 5 taps), refill LDG hoisted to top of iteration with a 7-slot
//     rotating window (distance-2 prefetch). Masks staged pre-permuted.

#define FH 64
#define FW 64
#define C2 128     // 256 channels / 2 (float2 groups)
#define OH 128
#define OW 128
#define KK 25
#define SEGW 8
#define NSLOT 7

__device__ __forceinline__ void fma2s(float2& a, const float2 f, const float m) {
    a.x = fmaf(f.x, m, a.x);
    a.y = fmaf(f.y, m, a.y);
}

template<bool CHK>
__device__ __forceinline__ void carafe_body(int seg, int hs, int b,
                                            const float2* __restrict__ F,
                                            float2* __restrict__ O,
                                            const float* __restrict__ smask,
                                            int c2)
{
    const int ws0 = seg * SEGW;
    const float2 z = make_float2(0.f, 0.f);

    // single feature base at (row hs-2, col ws0-2); all accesses below use
    // compile-time immediate offsets.
    const float2* fb = F + ((b * FH + (hs - 2)) * FW + (ws0 - 2)) * C2 + c2;

    bool rok[5];
    #pragma unroll
    for (int r = 0; r < 5; r++) {
        int hr = hs - 2 + r;
        rok[r] = CHK ? (hr >= 0 && hr < FH) : true;
    }

    // rotating window, slot(col) = (col - ws0 + 2) % 7.
    // initial fill: cols ws0-2 .. ws0+3 -> slots 0..5 (30 independent LDGs).
    float2 w[5][NSLOT];
    #pragma unroll
    for (int j = 0; j < 6; j++) {
        bool cok = CHK ? ((ws0 - 2 + j) >= 0 && (ws0 - 2 + j) < FW) : true;
        #pragma unroll
        for (int r = 0; r < 5; r++)
            w[r][j] = (rok[r] && cok) ? fb[(r * FW + j) * C2] : z;
    }

    float2* ob = O + ((b * OH + 2 * hs) * OW + 2 * ws0) * C2 + c2;

    #pragma unroll
    for (int s = 0; s < SEGW; s++) {
        // distance-2 prefetch: col ws0+s+4 (first used at iter s+2) into slot
        // (s+6)%7, which last held col ws0+s-3 (dead since iter s-1).
        if (s <= SEGW - 3) {
            const bool cok = CHK ? ((ws0 + s + 4) < FW) : true;
            #pragma unroll
            for (int r = 0; r < 5; r++)
                w[r][(s + 6) % NSLOT] =
                    (rok[r] && cok) ? fb[(r * FW + (s + 6)) * C2] : z;
        }

        const float4* __restrict__ mp = (const float4*)(smask + s * (KK * 4));

        float2 a0 = z, a1 = z, a2 = z, a3 = z;

        // d-major taps: pp = d*5 + r; newest column (d=4) hit only in the
        // last 5 taps. Masks were staged pre-permuted to match.
        #pragma unroll
        for (int pp = 0; pp < KK; pp++) {
            const int d = pp / 5;
            const int r = pp % 5;
            const float2 f = w[r][(s + d) % NSLOT];   // compile-time slot
            const float4 m = mp[pp];                  // broadcast LDS.128
            fma2s(a0, f, m.x);
            fma2s(a1, f, m.y);
            fma2s(a2, f, m.z);
            fma2s(a3, f, m.w);
        }

        ob[(2 * s) * C2]          = a0;
        ob[(2 * s + 1) * C2]      = a1;
        ob[(OW + 2 * s) * C2]     = a2;
        ob[(OW + 2 * s + 1) * C2] = a3;
    }
}

__global__ __launch_bounds__(128)
void carafe_kernel(const float* __restrict__ features,
                   const float* __restrict__ masks,
                   float* __restrict__ out)
{
    // smask layout: [px(8)][pp(25)][out(4)], pp = d*5 + r (d-major), out = oy*2+ox
    __shared__ __align__(16) float smask[SEGW * KK * 4];

    const int tid = threadIdx.x;
    const int seg = blockIdx.x;
    const int hs  = blockIdx.y;
    const int b   = blockIdx.z;
    const int ws0 = seg * SEGW;

    // cooperative mask stage with tap permutation r*5+d -> d*5+r
    {
        const int mrow0 = ((b * OH + 2 * hs    ) * OW + 2 * ws0) * KK;
        const int mrow1 = ((b * OH + 2 * hs + 1) * OW + 2 * ws0) * KK;
        #pragma unroll
        for (int it = 0; it < 7; it++) {
            int idx = tid + it * 128;
            if (idx < 800) {
                int oy   = idx / 400;
                int j    = idx - oy * 400;     // contiguous in global mask row
                int wrel = j / KK;             // 0..15 output col in segment
                int p    = j - wrel * KK;      // source tap index (r*5+d)
                int r    = p / 5;
                int d    = p - r * 5;
                int pp   = d * 5 + r;          // d-major position
                int px   = wrel >> 1;
                int ox   = wrel & 1;
                float v = masks[(oy ? mrow1 : mrow0) + j];
                smask[px * (KK * 4) + pp * 4 + oy * 2 + ox] = v;
            }
        }
    }
    __syncthreads();

    const float2* F = (const float2*)features;
    float2* O = (float2*)out;

    const bool interior = (seg >= 1) && (seg <= 6) && (hs >= 2) && (hs <= 61);
    if (interior)
        carafe_body<false>(seg, hs, b, F, O, smask, tid);
    else
        carafe_body<true>(seg, hs, b, F, O, smask, tid);
}

extern "C" void kernel_launch(void* const* d_in, const int* in_sizes, int n_in,
                              void* d_out, int out_size) {
    const float* features = (const float*)d_in[0];
    const float* masks    = (const float*)d_in[1];
    float* out            = (float*)d_out;

    dim3 grid(FW / SEGW, FH, 2);   // (8, 64, 2) = 1024 blocks x 4 warps
    carafe_kernel<<<grid, 128>>>(features, masks, out);
}

// round 8
// speedup vs baseline: 1.2159x; 1.1364x over previous
#include <cuda_runtime.h>

// CARAFE: features [2,64,64,256] f32, masks [2,128,128,25] f32, k=5, group=1.
// Nearest 64->128 half-pixel => src = dst >> 1; each source pixel feeds a 2x2
// output block sharing its 5x5 patch.
// R8: R4 skeleton (5-slot rotating float2 window, 50 regs, immediate offsets,
//     interior/border split) + d-major tap order so the column refilled at the
//     end of iteration s is first consumed ~160 FFMA-slots later (tap d=4 of
//     iteration s+1) -> window-refill LDG latency fully covered.

#define FH 64
#define FW 64
#define C2 128     // 256 channels / 2 (float2 groups)
#define OH 128
#define OW 128
#define KK 25
#define SEGW 8

__device__ __forceinline__ void fma2s(float2& a, const float2 f, const float m) {
    a.x = fmaf(f.x, m, a.x);
    a.y = fmaf(f.y, m, a.y);
}

template<bool CHK>
__device__ __forceinline__ void carafe_body(int seg, int hs, int b,
                                            const float2* __restrict__ F,
                                            float2* __restrict__ O,
                                            const float* __restrict__ smask,
                                            int c2)
{
    const int ws0 = seg * SEGW;
    const float2 z = make_float2(0.f, 0.f);

    // single feature base at (row hs-2, col ws0-2); all accesses below are
    // compile-time immediate offsets.
    const float2* fb = F + ((b * FH + (hs - 2)) * FW + (ws0 - 2)) * C2 + c2;

    bool rok[5];
    #pragma unroll
    for (int r = 0; r < 5; r++) {
        int hr = hs - 2 + r;
        rok[r] = CHK ? (hr >= 0 && hr < FH) : true;
    }

    // 5-slot rotating window: col (ws0-2+j) -> slot j (mod 5)
    float2 w[5][5];
    #pragma unroll
    for (int j = 0; j < 5; j++) {
        bool cok = CHK ? ((ws0 - 2 + j) >= 0 && (ws0 - 2 + j) < FW) : true;
        #pragma unroll
        for (int r = 0; r < 5; r++)
            w[r][j] = (rok[r] && cok) ? fb[(r * FW + j) * C2] : z;
    }

    float2* ob = O + ((b * OH + 2 * hs) * OW + 2 * ws0) * C2 + c2;

    #pragma unroll
    for (int s = 0; s < SEGW; s++) {
        const float4* __restrict__ mp = (const float4*)(smask + s * (KK * 4));

        float2 a0 = z, a1 = z, a2 = z, a3 = z;

        // d-major taps: pp = d*5 + r. The slot refilled at the end of iter s-1
        // (holding col ws0+s+2, i.e. d=4 for iter s) is consumed only in the
        // last 5 taps here. Masks staged pre-permuted to match.
        #pragma unroll
        for (int pp = 0; pp < KK; pp++) {
            const int d = pp / 5;
            const int r = pp % 5;
            const float2 f = w[r][(s + d) % 5];   // compile-time slot
            const float4 m = mp[pp];              // broadcast LDS.128
            fma2s(a0, f, m.x);
            fma2s(a1, f, m.y);
            fma2s(a2, f, m.z);
            fma2s(a3, f, m.w);
        }

        ob[(2 * s) * C2]          = a0;
        ob[(2 * s + 1) * C2]      = a1;
        ob[(OW + 2 * s) * C2]     = a2;
        ob[(OW + 2 * s + 1) * C2] = a3;

        if (s < SEGW - 1) {
            // refill col (ws0+s+3) into slot s%5 (dead after this iteration's
            // d=0 taps); first consumed at iter s+1, d=4 (last 5 taps).
            const bool cok = CHK ? ((ws0 + s + 3) < FW) : true;
            #pragma unroll
            for (int r = 0; r < 5; r++)
                w[r][s % 5] = (rok[r] && cok) ? fb[(r * FW + (s + 5)) * C2] : z;
        }
    }
}

__global__ __launch_bounds__(128)
void carafe_kernel(const float* __restrict__ features,
                   const float* __restrict__ masks,
                   float* __restrict__ out)
{
    // smask layout: [px(8)][pp(25)][out(4)], pp = d*5+r (d-major), out = oy*2+ox
    __shared__ __align__(16) float smask[SEGW * KK * 4];

    const int tid = threadIdx.x;
    const int seg = blockIdx.x;
    const int hs  = blockIdx.y;
    const int b   = blockIdx.z;
    const int ws0 = seg * SEGW;

    // cooperative mask stage with tap permutation r*5+d -> d*5+r
    {
        const int mrow0 = ((b * OH + 2 * hs    ) * OW + 2 * ws0) * KK;
        const int mrow1 = ((b * OH + 2 * hs + 1) * OW + 2 * ws0) * KK;
        #pragma unroll
        for (int it = 0; it < 7; it++) {
            int idx = tid + it * 128;
            if (idx < 800) {
                int oy   = idx / 400;
                int j    = idx - oy * 400;     // contiguous in global mask row
                int wrel = j / KK;             // 0..15 output col in segment
                int p    = j - wrel * KK;      // source tap index (r*5+d)
                int r    = p / 5;
                int d    = p - r * 5;
                int pp   = d * 5 + r;          // d-major position
                int px   = wrel >> 1;
                int ox   = wrel & 1;
                float v = masks[(oy ? mrow1 : mrow0) + j];
                smask[px * (KK * 4) + pp * 4 + oy * 2 + ox] = v;
            }
        }
    }
    __syncthreads();

    const float2* F = (const float2*)features;
    float2* O = (float2*)out;

    const bool interior = (seg >= 1) && (seg <= 6) && (hs >= 2) && (hs <= 61);
    if (interior)
        carafe_body<false>(seg, hs, b, F, O, smask, tid);
    else
        carafe_body<true>(seg, hs, b, F, O, smask, tid);
}

extern "C" void kernel_launch(void* const* d_in, const int* in_sizes, int n_in,
                              void* d_out, int out_size) {
    const float* features = (const float*)d_in[0];
    const float* masks    = (const float*)d_in[1];
    float* out            = (float*)d_out;

    dim3 grid(FW / SEGW, FH, 2);   // (8, 64, 2) = 1024 blocks x 4 warps
    carafe_kernel<<<grid, 128>>>(features, masks, out);
}